// round 13
// baseline (speedup 1.0000x reference)
#include <cuda_runtime.h>
#include <cuda_bf16.h>
#include <cuda_fp16.h>
#include <math.h>
#include <stdint.h>

#define BB   32
#define CC   256
#define CQ   64
#define HW   4096
#define CHW  (CC*HW)
#define DD   (CQ*HW)

__device__ __half g_Qh[(size_t)BB*DD];
__device__ __half g_Kh[(size_t)BB*DD];
__device__ float g_energy[BB*BB];
__device__ float g_att[BB*BB];
__device__ uint4 g_y_bf[(size_t)BB*CHW/8];     // bf16 [i][c][p]
__device__ uint4 g_Wv_bf[CC*CC/8];             // bf16 [o][c]
__device__ uint16_t g_Wqk[2*128*256];          // bf16 [w][(Wh;Wl) 128 rows][c]

// ---------------------------------------------------------------------------
__device__ __forceinline__ void mma_bf16(
    float* c, const uint32_t* a, uint32_t b0, uint32_t b1)
{
    asm volatile(
        "mma.sync.aligned.m16n8k16.row.col.f32.bf16.bf16.f32 "
        "{%0,%1,%2,%3}, {%4,%5,%6,%7}, {%8,%9}, {%0,%1,%2,%3};"
        : "+f"(c[0]), "+f"(c[1]), "+f"(c[2]), "+f"(c[3])
        : "r"(a[0]), "r"(a[1]), "r"(a[2]), "r"(a[3]), "r"(b0), "r"(b1));
}
__device__ __forceinline__ void mma_f16(
    float* c, const uint32_t* a, uint32_t b0, uint32_t b1)
{
    asm volatile(
        "mma.sync.aligned.m16n8k16.row.col.f32.f16.f16.f32 "
        "{%0,%1,%2,%3}, {%4,%5,%6,%7}, {%8,%9}, {%0,%1,%2,%3};"
        : "+f"(c[0]), "+f"(c[1]), "+f"(c[2]), "+f"(c[3])
        : "r"(a[0]), "r"(a[1]), "r"(a[2]), "r"(a[3]), "r"(b0), "r"(b1));
}
__device__ __forceinline__ void ldsm_x4(
    uint32_t& r0, uint32_t& r1, uint32_t& r2, uint32_t& r3, uint32_t addr)
{
    asm volatile("ldmatrix.sync.aligned.m8n8.x4.shared.b16 {%0,%1,%2,%3}, [%4];"
        : "=r"(r0), "=r"(r1), "=r"(r2), "=r"(r3) : "r"(addr));
}
__device__ __forceinline__ void ldsm_x2(
    uint32_t& r0, uint32_t& r1, uint32_t addr)
{
    asm volatile("ldmatrix.sync.aligned.m8n8.x2.shared.b16 {%0,%1}, [%2];"
        : "=r"(r0), "=r"(r1) : "r"(addr));
}
__device__ __forceinline__ void ldsm_x4_t(
    uint32_t& r0, uint32_t& r1, uint32_t& r2, uint32_t& r3, uint32_t addr)
{
    asm volatile("ldmatrix.sync.aligned.m8n8.x4.trans.shared.b16 {%0,%1,%2,%3}, [%4];"
        : "=r"(r0), "=r"(r1), "=r"(r2), "=r"(r3) : "r"(addr));
}
__device__ __forceinline__ uint16_t bfb(__nv_bfloat16 h) {
    uint16_t u; memcpy(&u, &h, 2); return u;
}

// ---------------------------------------------------------------------------
__global__ __launch_bounds__(256) void k_prep(
    const float* __restrict__ Wq, const float* __restrict__ Wk,
    const float* __restrict__ Wv)
{
    int t = blockIdx.x * 256 + threadIdx.x;
    int stride = gridDim.x * 256;
    for (int i = t; i < 2*CQ*CC; i += stride) {
        int w = i >> 14, rem = i & 16383;
        int o = rem >> 8, c = rem & 255;
        float f = (w ? Wk : Wq)[o*CC + c];
        __nv_bfloat16 h = __float2bfloat16(f);
        __nv_bfloat16 l = __float2bfloat16(f - __bfloat162float(h));
        g_Wqk[w*32768 + o*CC + c]      = bfb(h);
        g_Wqk[w*32768 + (o+64)*CC + c] = bfb(l);
    }
    __nv_bfloat16* wv = (__nv_bfloat16*)g_Wv_bf;
    for (int i = t; i < CC*CC; i += stride)
        wv[i] = __float2bfloat16(Wv[i]);
}

__global__ void k_zero_energy() {
    int t = threadIdx.x;
    if (t < BB*BB) g_energy[t] = 0.0f;
}

// ---------------------------------------------------------------------------
// Q/K projection (unchanged from R11; measured-good)
__global__ __launch_bounds__(256) void k_proj_bf16(
    const float* __restrict__ x0, const float* __restrict__ x1,
    const float* __restrict__ bq, const float* __restrict__ bk)
{
    const int which = blockIdx.z;
    const int b  = blockIdx.y;
    const int p0 = blockIdx.x * 64;
    const float* __restrict__ x    = which ? x1 : x0;
    const float* __restrict__ bias = which ? bk : bq;
    __half* __restrict__ outp      = which ? g_Kh : g_Qh;

    const int t = threadIdx.x;
    const int lane = t & 31, warp = t >> 5;
    const int mg = warp >> 1, np = warp & 1;
    const int rsel = lane & 15, half = lane >> 4;
    const int gid = lane >> 2, tig = lane & 3;

    __shared__ __align__(16) char smraw[33792];
    uint16_t* ws = (uint16_t*)smraw;               // [128][40]
    uint16_t* xh = (uint16_t*)(smraw + 10240);     // [32][136]
    uint16_t* xl = (uint16_t*)(smraw + 18944);     // [32][136]
    float* stage = (float*)smraw;                  // [128][66]
    const uint32_t ws_b = (uint32_t)__cvta_generic_to_shared(ws);
    const uint32_t xh_b = (uint32_t)__cvta_generic_to_shared(xh);
    const uint32_t xl_b = (uint32_t)__cvta_generic_to_shared(xl);

    float C[2][4][4];
    #pragma unroll
    for (int mf = 0; mf < 2; mf++)
        #pragma unroll
        for (int nf = 0; nf < 4; nf++)
            #pragma unroll
            for (int i = 0; i < 4; i++) C[mf][nf][i] = 0.0f;

    const uint16_t* wsrc = g_Wqk + which*32768;
    const float* xb = x + (size_t)b * CHW + p0;

    for (int cc = 0; cc < CC; cc += 32) {
        __syncthreads();
        #pragma unroll
        for (int r = 0; r < 2; r++) {
            int idx = r * 256 + t;
            int row = idx >> 2, c8 = idx & 3;
            *reinterpret_cast<uint4*>(&ws[row*40 + c8*8]) =
                *reinterpret_cast<const uint4*>(&wsrc[row*CC + cc + c8*8]);
        }
        #pragma unroll
        for (int r = 0; r < 2; r++) {
            int idx = r * 256 + t;
            int c = idx >> 4, p4 = idx & 15;
            float4 v = *reinterpret_cast<const float4*>(
                xb + (size_t)(cc + c) * HW + p4 * 4);
            __nv_bfloat16 h0 = __float2bfloat16(v.x), h1 = __float2bfloat16(v.y);
            __nv_bfloat16 h2 = __float2bfloat16(v.z), h3 = __float2bfloat16(v.w);
            uint2 hp, lp;
            hp.x = (uint32_t)bfb(h0) | ((uint32_t)bfb(h1) << 16);
            hp.y = (uint32_t)bfb(h2) | ((uint32_t)bfb(h3) << 16);
            lp.x = (uint32_t)bfb(__float2bfloat16(v.x - __bfloat162float(h0)))
                 | ((uint32_t)bfb(__float2bfloat16(v.y - __bfloat162float(h1))) << 16);
            lp.y = (uint32_t)bfb(__float2bfloat16(v.z - __bfloat162float(h2)))
                 | ((uint32_t)bfb(__float2bfloat16(v.w - __bfloat162float(h3))) << 16);
            *reinterpret_cast<uint2*>(&xh[c*136 + p4*4]) = hp;
            *reinterpret_cast<uint2*>(&xl[c*136 + p4*4]) = lp;
        }
        __syncthreads();

        #pragma unroll
        for (int kk = 0; kk < 2; kk++) {
            uint32_t A[2][4];
            #pragma unroll
            for (int mf = 0; mf < 2; mf++) {
                uint32_t addr = ws_b +
                    (uint32_t)((mg*32 + mf*16 + rsel)*80 + kk*32 + half*16);
                ldsm_x4(A[mf][0], A[mf][1], A[mf][2], A[mf][3], addr);
            }
            uint32_t Bh[2][4], Bl[2][4];
            #pragma unroll
            for (int n2 = 0; n2 < 2; n2++) {
                uint32_t off = (uint32_t)((kk*16 + rsel)*272 + (np*32 + n2*16 + half*8)*2);
                ldsm_x4_t(Bh[n2][0], Bh[n2][1], Bh[n2][2], Bh[n2][3], xh_b + off);
                ldsm_x4_t(Bl[n2][0], Bl[n2][1], Bl[n2][2], Bl[n2][3], xl_b + off);
            }
            #pragma unroll
            for (int mf = 0; mf < 2; mf++)
                #pragma unroll
                for (int nf = 0; nf < 4; nf++) {
                    mma_bf16(C[mf][nf], A[mf],
                             Bh[nf>>1][(nf&1)*2], Bh[nf>>1][(nf&1)*2 + 1]);
                    mma_bf16(C[mf][nf], A[mf],
                             Bl[nf>>1][(nf&1)*2], Bl[nf>>1][(nf&1)*2 + 1]);
                }
        }
    }

    __syncthreads();
    #pragma unroll
    for (int mf = 0; mf < 2; mf++)
        #pragma unroll
        for (int nf = 0; nf < 4; nf++) {
            int row = mg*32 + mf*16 + gid;
            int col = np*32 + nf*8 + tig*2;
            stage[row*66 + col]       = C[mf][nf][0];
            stage[row*66 + col + 1]   = C[mf][nf][1];
            stage[(row+8)*66 + col]   = C[mf][nf][2];
            stage[(row+8)*66 + col+1] = C[mf][nf][3];
        }
    __syncthreads();
    #pragma unroll
    for (int r = 0; r < 8; r++) {
        int idx = r * 512 + t * 2;
        int o = idx >> 6, p = idx & 63;
        float bb = bias[o];
        __half2 v = __floats2half2_rn(
            stage[o*66 + p]     + stage[(o+64)*66 + p]     + bb,
            stage[o*66 + p + 1] + stage[(o+64)*66 + p + 1] + bb);
        *reinterpret_cast<__half2*>(&outp[((size_t)b*CQ + o)*HW + p0 + p]) = v;
    }
}

// ---------------------------------------------------------------------------
// energy via fp16 mma (unchanged; measured 18us)
__global__ __launch_bounds__(256) void k_energy()
{
    __shared__ __align__(16) char smbuf[34816];
    uint16_t* Kt = (uint16_t*)smbuf;
    uint16_t* Qt = Kt + 32*264;
    float* red = (float*)smbuf;

    const int t = threadIdx.x;
    const int lane = t & 31, warp = t >> 5;
    const int gid = lane >> 2, tig = lane & 3;
    const int d0 = blockIdx.x * 2048;
    const uint32_t kt_b = (uint32_t)__cvta_generic_to_shared(Kt);
    const uint32_t qt_b = (uint32_t)__cvta_generic_to_shared(Qt);

    float C[2][4][4];
    #pragma unroll
    for (int mt = 0; mt < 2; mt++)
        #pragma unroll
        for (int nt = 0; nt < 4; nt++)
            #pragma unroll
            for (int i = 0; i < 4; i++) C[mt][nt][i] = 0.0f;

    for (int tile = 0; tile < 8; tile++) {
        const int dt = d0 + tile * 256;
        __syncthreads();
        #pragma unroll
        for (int r = 0; r < 4; r++) {
            int idx = r * 256 + t;
            int row = idx >> 5, c4 = idx & 31;
            *reinterpret_cast<uint4*>(&Kt[row*264 + c4*8]) =
                *reinterpret_cast<const uint4*>(&g_Kh[(size_t)row*DD + dt + c4*8]);
            *reinterpret_cast<uint4*>(&Qt[row*264 + c4*8]) =
                *reinterpret_cast<const uint4*>(&g_Qh[(size_t)row*DD + dt + c4*8]);
        }
        __syncthreads();
        #pragma unroll
        for (int ss = 0; ss < 2; ss++) {
            const int ds = (warp * 2 + ss) * 16;
            uint32_t A[2][4];
            #pragma unroll
            for (int mt = 0; mt < 2; mt++) {
                uint32_t addr = kt_b +
                    (uint32_t)(((mt*16 + (lane & 15))*264 + ds + (lane >> 4)*8) * 2);
                ldsm_x4(A[mt][0], A[mt][1], A[mt][2], A[mt][3], addr);
            }
            #pragma unroll
            for (int nt = 0; nt < 4; nt++) {
                uint32_t b0, b1;
                uint32_t addr = qt_b +
                    (uint32_t)(((nt*8 + (lane & 7))*264 + ds + ((lane >> 3) & 1)*8) * 2);
                ldsm_x2(b0, b1, addr);
                #pragma unroll
                for (int mt = 0; mt < 2; mt++)
                    mma_f16(C[mt][nt], A[mt], b0, b1);
            }
        }
    }
    __syncthreads();
    #pragma unroll
    for (int mt = 0; mt < 2; mt++)
        #pragma unroll
        for (int nt = 0; nt < 4; nt++) {
            int row = mt*16 + gid, col = nt*8 + tig*2;
            float* rw = red + warp*1024;
            rw[row*32 + col]       = C[mt][nt][0];
            rw[row*32 + col + 1]   = C[mt][nt][1];
            rw[(row+8)*32 + col]   = C[mt][nt][2];
            rw[(row+8)*32 + col+1] = C[mt][nt][3];
        }
    __syncthreads();
    #pragma unroll
    for (int r = 0; r < 4; r++) {
        int idx = r * 256 + t;
        float s = 0.f;
        #pragma unroll
        for (int w = 0; w < 8; w++) s += red[w*1024 + idx];
        atomicAdd(&g_energy[idx], s);
    }
}

// ---------------------------------------------------------------------------
__global__ void k_softmax(float* __restrict__ att_out)
{
    int i = threadIdx.x;
    if (i >= BB) return;
    float e[BB];
    float m = -INFINITY;
    #pragma unroll
    for (int j = 0; j < BB; j++) { e[j] = g_energy[i*BB + j]; m = fmaxf(m, e[j]); }
    float s = 0.f;
    #pragma unroll
    for (int j = 0; j < BB; j++) { e[j] = expf(e[j] - m); s += e[j]; }
    float inv = 1.0f / s;
    #pragma unroll
    for (int j = 0; j < BB; j++) {
        float a = e[j] * inv;
        g_att[i*BB + j] = a;
        if (att_out) att_out[i*BB + j] = a;
    }
}

// ---------------------------------------------------------------------------
__global__ __launch_bounds__(256) void k_mix(const float* __restrict__ x0)
{
    __shared__ float att_s[BB*BB];
    const int t = threadIdx.x;
    #pragma unroll
    for (int r = 0; r < 4; r++) att_s[r*256 + t] = g_att[r*256 + t];
    __syncthreads();

    const size_t cp = ((size_t)blockIdx.x * 256 + t) * 2;
    float2 acc[BB];
    #pragma unroll
    for (int i = 0; i < BB; i++) acc[i] = make_float2(0.f, 0.f);

    #pragma unroll
    for (int j = 0; j < BB; j++) {
        float2 v = *reinterpret_cast<const float2*>(&x0[(size_t)j * CHW + cp]);
        #pragma unroll
        for (int i = 0; i < BB; i++) {
            float a = att_s[i*BB + j];
            acc[i].x += a * v.x;
            acc[i].y += a * v.y;
        }
    }
    uint32_t* y2 = (uint32_t*)g_y_bf;
    const size_t base = (size_t)blockIdx.x * 256 + t;
    #pragma unroll
    for (int i = 0; i < BB; i++) {
        __nv_bfloat162 bv = __floats2bfloat162_rn(acc[i].x, acc[i].y);
        y2[(size_t)i * (CHW/2) + base] = *reinterpret_cast<uint32_t*>(&bv);
    }
}

// ---------------------------------------------------------------------------
// out = gamma*(Wv y + bv) + x1.  NEW tiling: o-tile 256 (all), p-tile 64.
// 512 threads = 16 warps: wo 0..3 (o64) x wp 0..3 (p16). Warp m64 x n16.
// y read exactly once (no o-tile amplification); Wv re-reads hit L2.
__global__ __launch_bounds__(512) void k_out_bf16(
    const float* __restrict__ x1, const float* __restrict__ bv,
    const float* __restrict__ gamma, float* __restrict__ outp)
{
    const int b  = blockIdx.y;
    const int p0 = blockIdx.x * 64;
    const int t    = threadIdx.x;
    const int lane = t & 31, warp = t >> 5;
    const int wo = warp >> 2, wp = warp & 3;
    const int rsel = lane & 15, half = lane >> 4;
    const int gid = lane >> 2, tig = lane & 3;

    __shared__ __align__(16) uint16_t ws[256*40];   // [o][c] 80B rows
    __shared__ __align__(16) uint16_t ys[32*72];    // [c][p] 144B rows (16 mod 128)
    const uint32_t ws_b = (uint32_t)__cvta_generic_to_shared(ws);
    const uint32_t ys_b = (uint32_t)__cvta_generic_to_shared(ys);

    float C[4][2][4];
    #pragma unroll
    for (int mf = 0; mf < 4; mf++)
        #pragma unroll
        for (int nf = 0; nf < 2; nf++)
            #pragma unroll
            for (int i = 0; i < 4; i++) C[mf][nf][i] = 0.0f;

    const __nv_bfloat16* ybase = (const __nv_bfloat16*)g_y_bf + (size_t)b * CHW + p0;
    const __nv_bfloat16* wvb   = (const __nv_bfloat16*)g_Wv_bf;

    for (int cc = 0; cc < CC; cc += 32) {
        __syncthreads();
        // ws: 256 o x 32 c = 1024 uint4, 2/thread
        #pragma unroll
        for (int r = 0; r < 2; r++) {
            int idx = r * 512 + t;
            int row = idx >> 2, ch = idx & 3;
            *reinterpret_cast<uint4*>(&ws[row*40 + ch*8]) =
                *reinterpret_cast<const uint4*>(wvb + (size_t)row*CC + cc + ch*8);
        }
        // ys: 32 c x 64 p = 256 uint4, threads 0..255
        if (t < 256) {
            int row = t >> 3, ch = t & 7;
            *reinterpret_cast<uint4*>(&ys[row*72 + ch*8]) =
                *reinterpret_cast<const uint4*>(ybase + (size_t)(cc + row)*HW + ch*8);
        }
        __syncthreads();

        #pragma unroll
        for (int kk = 0; kk < 2; kk++) {
            uint32_t A[4][4];
            #pragma unroll
            for (int mf = 0; mf < 4; mf++) {
                uint32_t addr = ws_b +
                    (uint32_t)((wo*64 + mf*16 + rsel)*80 + kk*32 + half*16);
                ldsm_x4(A[mf][0], A[mf][1], A[mf][2], A[mf][3], addr);
            }
            uint32_t Bf[4];
            {
                uint32_t addr = ys_b +
                    (uint32_t)((kk*16 + rsel)*144 + (wp*16 + half*8)*2);
                ldsm_x4_t(Bf[0], Bf[1], Bf[2], Bf[3], addr);
            }
            #pragma unroll
            for (int mf = 0; mf < 4; mf++)
                #pragma unroll
                for (int nf = 0; nf < 2; nf++)
                    mma_bf16(C[mf][nf], A[mf], Bf[nf*2], Bf[nf*2 + 1]);
        }
    }

    const float g = gamma[0];
    #pragma unroll
    for (int mf = 0; mf < 4; mf++) {
        const int o = wo*64 + mf*16 + gid;
        const float bv0 = bv[o], bv1 = bv[o + 8];
        #pragma unroll
        for (int nf = 0; nf < 2; nf++) {
            const int p = p0 + wp*16 + nf*8 + tig*2;
            size_t gi0 = ((size_t)b * CC + o) * HW + p;
            size_t gi1 = gi0 + (size_t)8 * HW;
            float2 xa = *reinterpret_cast<const float2*>(&x1[gi0]);
            float2 xc = *reinterpret_cast<const float2*>(&x1[gi1]);
            float2 r0, r1;
            r0.x = g * (C[mf][nf][0] + bv0) + xa.x;
            r0.y = g * (C[mf][nf][1] + bv0) + xa.y;
            r1.x = g * (C[mf][nf][2] + bv1) + xc.x;
            r1.y = g * (C[mf][nf][3] + bv1) + xc.y;
            *reinterpret_cast<float2*>(&outp[gi0]) = r0;
            *reinterpret_cast<float2*>(&outp[gi1]) = r1;
        }
    }
}

// ---------------------------------------------------------------------------
extern "C" void kernel_launch(void* const* d_in, const int* in_sizes, int n_in,
                              void* d_out, int out_size)
{
    const float* x0    = (const float*)d_in[0];
    const float* x1    = (const float*)d_in[1];
    const float* Wq    = (const float*)d_in[2];
    const float* bq    = (const float*)d_in[3];
    const float* Wk    = (const float*)d_in[4];
    const float* bk    = (const float*)d_in[5];
    const float* Wv    = (const float*)d_in[6];
    const float* bv    = (const float*)d_in[7];
    const float* gamma = (const float*)d_in[8];
    float* out = (float*)d_out;

    const long long out_elems = (long long)BB * CC * HW;
    float* att_out = ((long long)out_size >= out_elems + BB*BB)
                     ? out + out_elems : nullptr;

    k_prep<<<32, 256>>>(Wq, Wk, Wv);
    k_zero_energy<<<1, 1024>>>();
    k_proj_bf16<<<dim3(HW/64, BB, 2), 256>>>(x0, x1, bq, bk);
    k_energy<<<DD/2048, 256>>>();
    k_softmax<<<1, 32>>>(att_out);
    k_mix<<<CHW/512, 256>>>(x0);
    k_out_bf16<<<dim3(HW/64, BB), 512>>>(x1, bv, gamma, out);
}

// round 15
// speedup vs baseline: 1.0287x; 1.0287x over previous
#include <cuda_runtime.h>
#include <cuda_bf16.h>
#include <cuda_fp16.h>
#include <math.h>
#include <stdint.h>

#define BB   32
#define CC   256
#define CQ   64
#define HW   4096
#define CHW  (CC*HW)
#define DD   (CQ*HW)

__device__ __half g_Qh[(size_t)BB*DD];
__device__ __half g_Kh[(size_t)BB*DD];
__device__ float g_energy[BB*BB];
__device__ float g_att[BB*BB];
__device__ uint4 g_y_bf[(size_t)BB*CHW/8];     // bf16 [i][c][p]
__device__ uint4 g_Wv_bf[CC*CC/8];             // bf16 [o][c]
__device__ uint16_t g_Wqk[2*128*256];          // bf16 [w][(Wh;Wl) 128 rows][c]

// ---------------------------------------------------------------------------
__device__ __forceinline__ void mma_bf16(
    float* c, const uint32_t* a, uint32_t b0, uint32_t b1)
{
    asm volatile(
        "mma.sync.aligned.m16n8k16.row.col.f32.bf16.bf16.f32 "
        "{%0,%1,%2,%3}, {%4,%5,%6,%7}, {%8,%9}, {%0,%1,%2,%3};"
        : "+f"(c[0]), "+f"(c[1]), "+f"(c[2]), "+f"(c[3])
        : "r"(a[0]), "r"(a[1]), "r"(a[2]), "r"(a[3]), "r"(b0), "r"(b1));
}
__device__ __forceinline__ void mma_f16(
    float* c, const uint32_t* a, uint32_t b0, uint32_t b1)
{
    asm volatile(
        "mma.sync.aligned.m16n8k16.row.col.f32.f16.f16.f32 "
        "{%0,%1,%2,%3}, {%4,%5,%6,%7}, {%8,%9}, {%0,%1,%2,%3};"
        : "+f"(c[0]), "+f"(c[1]), "+f"(c[2]), "+f"(c[3])
        : "r"(a[0]), "r"(a[1]), "r"(a[2]), "r"(a[3]), "r"(b0), "r"(b1));
}
__device__ __forceinline__ void ldsm_x4(
    uint32_t& r0, uint32_t& r1, uint32_t& r2, uint32_t& r3, uint32_t addr)
{
    asm volatile("ldmatrix.sync.aligned.m8n8.x4.shared.b16 {%0,%1,%2,%3}, [%4];"
        : "=r"(r0), "=r"(r1), "=r"(r2), "=r"(r3) : "r"(addr));
}
__device__ __forceinline__ void ldsm_x2(
    uint32_t& r0, uint32_t& r1, uint32_t addr)
{
    asm volatile("ldmatrix.sync.aligned.m8n8.x2.shared.b16 {%0,%1}, [%2];"
        : "=r"(r0), "=r"(r1) : "r"(addr));
}
__device__ __forceinline__ void ldsm_x4_t(
    uint32_t& r0, uint32_t& r1, uint32_t& r2, uint32_t& r3, uint32_t addr)
{
    asm volatile("ldmatrix.sync.aligned.m8n8.x4.trans.shared.b16 {%0,%1,%2,%3}, [%4];"
        : "=r"(r0), "=r"(r1), "=r"(r2), "=r"(r3) : "r"(addr));
}
__device__ __forceinline__ uint16_t bfb(__nv_bfloat16 h) {
    uint16_t u; memcpy(&u, &h, 2); return u;
}

// ---------------------------------------------------------------------------
// Prep (+ energy zeroing folded in)
__global__ __launch_bounds__(256) void k_prep(
    const float* __restrict__ Wq, const float* __restrict__ Wk,
    const float* __restrict__ Wv)
{
    if (blockIdx.x == 0) {
        #pragma unroll
        for (int r = 0; r < 4; r++) g_energy[r*256 + threadIdx.x] = 0.0f;
    }
    int t = blockIdx.x * 256 + threadIdx.x;
    int stride = gridDim.x * 256;
    for (int i = t; i < 2*CQ*CC; i += stride) {
        int w = i >> 14, rem = i & 16383;
        int o = rem >> 8, c = rem & 255;
        float f = (w ? Wk : Wq)[o*CC + c];
        __nv_bfloat16 h = __float2bfloat16(f);
        __nv_bfloat16 l = __float2bfloat16(f - __bfloat162float(h));
        g_Wqk[w*32768 + o*CC + c]      = bfb(h);
        g_Wqk[w*32768 + (o+64)*CC + c] = bfb(l);
    }
    __nv_bfloat16* wv = (__nv_bfloat16*)g_Wv_bf;
    for (int i = t; i < CC*CC; i += stride)
        wv[i] = __float2bfloat16(Wv[i]);
}

// ---------------------------------------------------------------------------
// Q/K projection (R11 exact; measured-good)
__global__ __launch_bounds__(256) void k_proj_bf16(
    const float* __restrict__ x0, const float* __restrict__ x1,
    const float* __restrict__ bq, const float* __restrict__ bk)
{
    const int which = blockIdx.z;
    const int b  = blockIdx.y;
    const int p0 = blockIdx.x * 64;
    const float* __restrict__ x    = which ? x1 : x0;
    const float* __restrict__ bias = which ? bk : bq;
    __half* __restrict__ outp      = which ? g_Kh : g_Qh;

    const int t = threadIdx.x;
    const int lane = t & 31, warp = t >> 5;
    const int mg = warp >> 1, np = warp & 1;
    const int rsel = lane & 15, half = lane >> 4;
    const int gid = lane >> 2, tig = lane & 3;

    __shared__ __align__(16) char smraw[33792];
    uint16_t* ws = (uint16_t*)smraw;               // [128][40]
    uint16_t* xh = (uint16_t*)(smraw + 10240);     // [32][136]
    uint16_t* xl = (uint16_t*)(smraw + 18944);     // [32][136]
    float* stage = (float*)smraw;                  // [128][66]
    const uint32_t ws_b = (uint32_t)__cvta_generic_to_shared(ws);
    const uint32_t xh_b = (uint32_t)__cvta_generic_to_shared(xh);
    const uint32_t xl_b = (uint32_t)__cvta_generic_to_shared(xl);

    float C[2][4][4];
    #pragma unroll
    for (int mf = 0; mf < 2; mf++)
        #pragma unroll
        for (int nf = 0; nf < 4; nf++)
            #pragma unroll
            for (int i = 0; i < 4; i++) C[mf][nf][i] = 0.0f;

    const uint16_t* wsrc = g_Wqk + which*32768;
    const float* xb = x + (size_t)b * CHW + p0;

    for (int cc = 0; cc < CC; cc += 32) {
        __syncthreads();
        #pragma unroll
        for (int r = 0; r < 2; r++) {
            int idx = r * 256 + t;
            int row = idx >> 2, c8 = idx & 3;
            *reinterpret_cast<uint4*>(&ws[row*40 + c8*8]) =
                *reinterpret_cast<const uint4*>(&wsrc[row*CC + cc + c8*8]);
        }
        #pragma unroll
        for (int r = 0; r < 2; r++) {
            int idx = r * 256 + t;
            int c = idx >> 4, p4 = idx & 15;
            float4 v = *reinterpret_cast<const float4*>(
                xb + (size_t)(cc + c) * HW + p4 * 4);
            __nv_bfloat16 h0 = __float2bfloat16(v.x), h1 = __float2bfloat16(v.y);
            __nv_bfloat16 h2 = __float2bfloat16(v.z), h3 = __float2bfloat16(v.w);
            uint2 hp, lp;
            hp.x = (uint32_t)bfb(h0) | ((uint32_t)bfb(h1) << 16);
            hp.y = (uint32_t)bfb(h2) | ((uint32_t)bfb(h3) << 16);
            lp.x = (uint32_t)bfb(__float2bfloat16(v.x - __bfloat162float(h0)))
                 | ((uint32_t)bfb(__float2bfloat16(v.y - __bfloat162float(h1))) << 16);
            lp.y = (uint32_t)bfb(__float2bfloat16(v.z - __bfloat162float(h2)))
                 | ((uint32_t)bfb(__float2bfloat16(v.w - __bfloat162float(h3))) << 16);
            *reinterpret_cast<uint2*>(&xh[c*136 + p4*4]) = hp;
            *reinterpret_cast<uint2*>(&xl[c*136 + p4*4]) = lp;
        }
        __syncthreads();

        #pragma unroll
        for (int kk = 0; kk < 2; kk++) {
            uint32_t A[2][4];
            #pragma unroll
            for (int mf = 0; mf < 2; mf++) {
                uint32_t addr = ws_b +
                    (uint32_t)((mg*32 + mf*16 + rsel)*80 + kk*32 + half*16);
                ldsm_x4(A[mf][0], A[mf][1], A[mf][2], A[mf][3], addr);
            }
            uint32_t Bh[2][4], Bl[2][4];
            #pragma unroll
            for (int n2 = 0; n2 < 2; n2++) {
                uint32_t off = (uint32_t)((kk*16 + rsel)*272 + (np*32 + n2*16 + half*8)*2);
                ldsm_x4_t(Bh[n2][0], Bh[n2][1], Bh[n2][2], Bh[n2][3], xh_b + off);
                ldsm_x4_t(Bl[n2][0], Bl[n2][1], Bl[n2][2], Bl[n2][3], xl_b + off);
            }
            #pragma unroll
            for (int mf = 0; mf < 2; mf++)
                #pragma unroll
                for (int nf = 0; nf < 4; nf++) {
                    mma_bf16(C[mf][nf], A[mf],
                             Bh[nf>>1][(nf&1)*2], Bh[nf>>1][(nf&1)*2 + 1]);
                    mma_bf16(C[mf][nf], A[mf],
                             Bl[nf>>1][(nf&1)*2], Bl[nf>>1][(nf&1)*2 + 1]);
                }
        }
    }

    __syncthreads();
    #pragma unroll
    for (int mf = 0; mf < 2; mf++)
        #pragma unroll
        for (int nf = 0; nf < 4; nf++) {
            int row = mg*32 + mf*16 + gid;
            int col = np*32 + nf*8 + tig*2;
            stage[row*66 + col]       = C[mf][nf][0];
            stage[row*66 + col + 1]   = C[mf][nf][1];
            stage[(row+8)*66 + col]   = C[mf][nf][2];
            stage[(row+8)*66 + col+1] = C[mf][nf][3];
        }
    __syncthreads();
    #pragma unroll
    for (int r = 0; r < 8; r++) {
        int idx = r * 512 + t * 2;
        int o = idx >> 6, p = idx & 63;
        float bb = bias[o];
        __half2 v = __floats2half2_rn(
            stage[o*66 + p]     + stage[(o+64)*66 + p]     + bb,
            stage[o*66 + p + 1] + stage[(o+64)*66 + p + 1] + bb);
        *reinterpret_cast<__half2*>(&outp[((size_t)b*CQ + o)*HW + p0 + p]) = v;
    }
}

// ---------------------------------------------------------------------------
// energy via fp16 mma (unchanged; measured 18us)
__global__ __launch_bounds__(256) void k_energy()
{
    __shared__ __align__(16) char smbuf[34816];
    uint16_t* Kt = (uint16_t*)smbuf;
    uint16_t* Qt = Kt + 32*264;
    float* red = (float*)smbuf;

    const int t = threadIdx.x;
    const int lane = t & 31, warp = t >> 5;
    const int gid = lane >> 2, tig = lane & 3;
    const int d0 = blockIdx.x * 2048;
    const uint32_t kt_b = (uint32_t)__cvta_generic_to_shared(Kt);
    const uint32_t qt_b = (uint32_t)__cvta_generic_to_shared(Qt);

    float C[2][4][4];
    #pragma unroll
    for (int mt = 0; mt < 2; mt++)
        #pragma unroll
        for (int nt = 0; nt < 4; nt++)
            #pragma unroll
            for (int i = 0; i < 4; i++) C[mt][nt][i] = 0.0f;

    for (int tile = 0; tile < 8; tile++) {
        const int dt = d0 + tile * 256;
        __syncthreads();
        #pragma unroll
        for (int r = 0; r < 4; r++) {
            int idx = r * 256 + t;
            int row = idx >> 5, c4 = idx & 31;
            *reinterpret_cast<uint4*>(&Kt[row*264 + c4*8]) =
                *reinterpret_cast<const uint4*>(&g_Kh[(size_t)row*DD + dt + c4*8]);
            *reinterpret_cast<uint4*>(&Qt[row*264 + c4*8]) =
                *reinterpret_cast<const uint4*>(&g_Qh[(size_t)row*DD + dt + c4*8]);
        }
        __syncthreads();
        #pragma unroll
        for (int ss = 0; ss < 2; ss++) {
            const int ds = (warp * 2 + ss) * 16;
            uint32_t A[2][4];
            #pragma unroll
            for (int mt = 0; mt < 2; mt++) {
                uint32_t addr = kt_b +
                    (uint32_t)(((mt*16 + (lane & 15))*264 + ds + (lane >> 4)*8) * 2);
                ldsm_x4(A[mt][0], A[mt][1], A[mt][2], A[mt][3], addr);
            }
            #pragma unroll
            for (int nt = 0; nt < 4; nt++) {
                uint32_t b0, b1;
                uint32_t addr = qt_b +
                    (uint32_t)(((nt*8 + (lane & 7))*264 + ds + ((lane >> 3) & 1)*8) * 2);
                ldsm_x2(b0, b1, addr);
                #pragma unroll
                for (int mt = 0; mt < 2; mt++)
                    mma_f16(C[mt][nt], A[mt], b0, b1);
            }
        }
    }
    __syncthreads();
    #pragma unroll
    for (int mt = 0; mt < 2; mt++)
        #pragma unroll
        for (int nt = 0; nt < 4; nt++) {
            int row = mt*16 + gid, col = nt*8 + tig*2;
            float* rw = red + warp*1024;
            rw[row*32 + col]       = C[mt][nt][0];
            rw[row*32 + col + 1]   = C[mt][nt][1];
            rw[(row+8)*32 + col]   = C[mt][nt][2];
            rw[(row+8)*32 + col+1] = C[mt][nt][3];
        }
    __syncthreads();
    #pragma unroll
    for (int r = 0; r < 4; r++) {
        int idx = r * 256 + t;
        float s = 0.f;
        #pragma unroll
        for (int w = 0; w < 8; w++) s += red[w*1024 + idx];
        atomicAdd(&g_energy[idx], s);
    }
}

// ---------------------------------------------------------------------------
__global__ void k_softmax(float* __restrict__ att_out)
{
    int i = threadIdx.x;
    if (i >= BB) return;
    float e[BB];
    float m = -INFINITY;
    #pragma unroll
    for (int j = 0; j < BB; j++) { e[j] = g_energy[i*BB + j]; m = fmaxf(m, e[j]); }
    float s = 0.f;
    #pragma unroll
    for (int j = 0; j < BB; j++) { e[j] = expf(e[j] - m); s += e[j]; }
    float inv = 1.0f / s;
    #pragma unroll
    for (int j = 0; j < BB; j++) {
        float a = e[j] * inv;
        g_att[i*BB + j] = a;
        if (att_out) att_out[i*BB + j] = a;
    }
}

// ---------------------------------------------------------------------------
__global__ __launch_bounds__(256) void k_mix(const float* __restrict__ x0)
{
    __shared__ float att_s[BB*BB];
    const int t = threadIdx.x;
    #pragma unroll
    for (int r = 0; r < 4; r++) att_s[r*256 + t] = g_att[r*256 + t];
    __syncthreads();

    const size_t cp = ((size_t)blockIdx.x * 256 + t) * 2;
    float2 acc[BB];
    #pragma unroll
    for (int i = 0; i < BB; i++) acc[i] = make_float2(0.f, 0.f);

    #pragma unroll
    for (int j = 0; j < BB; j++) {
        float2 v = *reinterpret_cast<const float2*>(&x0[(size_t)j * CHW + cp]);
        #pragma unroll
        for (int i = 0; i < BB; i++) {
            float a = att_s[i*BB + j];
            acc[i].x += a * v.x;
            acc[i].y += a * v.y;
        }
    }
    uint32_t* y2 = (uint32_t*)g_y_bf;
    const size_t base = (size_t)blockIdx.x * 256 + t;
    #pragma unroll
    for (int i = 0; i < BB; i++) {
        __nv_bfloat162 bv = __floats2bfloat162_rn(acc[i].x, acc[i].y);
        y2[(size_t)i * (CHW/2) + base] = *reinterpret_cast<uint32_t*>(&bv);
    }
}

// ---------------------------------------------------------------------------
// out = gamma*(Wv y + bv) + x1.  R11 tiling; grid remapped so the 4 o-tiles
// sharing a y slice are launch-adjacent (x = o-tile) for guaranteed L2 reuse.
__global__ __launch_bounds__(256) void k_out_bf16(
    const float* __restrict__ x1, const float* __restrict__ bv,
    const float* __restrict__ gamma, float* __restrict__ outp)
{
    const int ot = blockIdx.x * 64;     // fastest: 4 o-tiles share y slice
    const int p0 = blockIdx.y * 128;
    const int b  = blockIdx.z;
    const int t    = threadIdx.x;
    const int lane = t & 31, warp = t >> 5;
    const int wo = warp >> 2, wp = warp & 3;
    const int obase = wo * 32, pbw = wp * 32;
    const int gid = lane >> 2, tig = lane & 3;

    __shared__ __align__(16) uint16_t ws[64*40];
    __shared__ __align__(16) uint16_t ys[32*136];
    const uint32_t ws_b = (uint32_t)__cvta_generic_to_shared(ws);
    const uint32_t ys_b = (uint32_t)__cvta_generic_to_shared(ys);

    float C[2][4][4];
    #pragma unroll
    for (int mf = 0; mf < 2; mf++)
        #pragma unroll
        for (int nf = 0; nf < 4; nf++)
            #pragma unroll
            for (int i = 0; i < 4; i++) C[mf][nf][i] = 0.0f;

    const __nv_bfloat16* ybase = (const __nv_bfloat16*)g_y_bf + (size_t)b * CHW + p0;
    const __nv_bfloat16* wvb   = (const __nv_bfloat16*)g_Wv_bf;

    for (int cc = 0; cc < CC; cc += 32) {
        __syncthreads();
        {
            int row = t >> 2, ch = t & 3;
            *reinterpret_cast<uint4*>(&ws[row*40 + ch*8]) =
                *reinterpret_cast<const uint4*>(wvb + (size_t)(ot + row)*CC + cc + ch*8);
        }
        #pragma unroll
        for (int r = 0; r < 2; r++) {
            int idx = r * 256 + t;
            int row = idx >> 4, ch = idx & 15;
            *reinterpret_cast<uint4*>(&ys[row*136 + ch*8]) =
                *reinterpret_cast<const uint4*>(ybase + (size_t)(cc + row)*HW + ch*8);
        }
        __syncthreads();

        #pragma unroll
        for (int kk = 0; kk < 2; kk++) {
            const int rsel = lane & 15;
            const int half = lane >> 4;
            uint32_t A[2][4];
            #pragma unroll
            for (int mf = 0; mf < 2; mf++) {
                uint32_t addr = ws_b + (uint32_t)((obase + mf*16 + rsel)*80 + kk*32 + half*16);
                ldsm_x4(A[mf][0], A[mf][1], A[mf][2], A[mf][3], addr);
            }
            uint32_t Bf[2][4];
            #pragma unroll
            for (int n2 = 0; n2 < 2; n2++) {
                uint32_t addr = ys_b + (uint32_t)((kk*16 + rsel)*272 + (pbw + n2*16 + half*8)*2);
                ldsm_x4_t(Bf[n2][0], Bf[n2][1], Bf[n2][2], Bf[n2][3], addr);
            }
            #pragma unroll
            for (int mf = 0; mf < 2; mf++)
                #pragma unroll
                for (int nf = 0; nf < 4; nf++)
                    mma_bf16(C[mf][nf], A[mf],
                             Bf[nf>>1][(nf&1)*2], Bf[nf>>1][(nf&1)*2 + 1]);
        }
    }

    const float g = gamma[0];
    #pragma unroll
    for (int mf = 0; mf < 2; mf++) {
        const int o = ot + obase + mf*16 + gid;
        const float bv0 = bv[o], bv1 = bv[o + 8];
        #pragma unroll
        for (int nf = 0; nf < 4; nf++) {
            const int p = p0 + pbw + nf*8 + tig*2;
            size_t gi0 = ((size_t)b * CC + o) * HW + p;
            size_t gi1 = gi0 + (size_t)8 * HW;
            float2 xa = *reinterpret_cast<const float2*>(&x1[gi0]);
            float2 xc = *reinterpret_cast<const float2*>(&x1[gi1]);
            float2 r0, r1;
            r0.x = g * (C[mf][nf][0] + bv0) + xa.x;
            r0.y = g * (C[mf][nf][1] + bv0) + xa.y;
            r1.x = g * (C[mf][nf][2] + bv1) + xc.x;
            r1.y = g * (C[mf][nf][3] + bv1) + xc.y;
            *reinterpret_cast<float2*>(&outp[gi0]) = r0;
            *reinterpret_cast<float2*>(&outp[gi1]) = r1;
        }
    }
}

// ---------------------------------------------------------------------------
extern "C" void kernel_launch(void* const* d_in, const int* in_sizes, int n_in,
                              void* d_out, int out_size)
{
    const float* x0    = (const float*)d_in[0];
    const float* x1    = (const float*)d_in[1];
    const float* Wq    = (const float*)d_in[2];
    const float* bq    = (const float*)d_in[3];
    const float* Wk    = (const float*)d_in[4];
    const float* bk    = (const float*)d_in[5];
    const float* Wv    = (const float*)d_in[6];
    const float* bv    = (const float*)d_in[7];
    const float* gamma = (const float*)d_in[8];
    float* out = (float*)d_out;

    const long long out_elems = (long long)BB * CC * HW;
    float* att_out = ((long long)out_size >= out_elems + BB*BB)
                     ? out + out_elems : nullptr;

    k_prep<<<32, 256>>>(Wq, Wk, Wv);
    k_proj_bf16<<<dim3(HW/64, BB, 2), 256>>>(x0, x1, bq, bk);
    k_energy<<<DD/2048, 256>>>();
    k_softmax<<<1, 32>>>(att_out);
    k_mix<<<CHW/512, 256>>>(x0);
    k_out_bf16<<<dim3(CC/64, HW/128, BB), 256>>>(x1, bv, gamma, out);
}

// round 16
// speedup vs baseline: 1.2505x; 1.2156x over previous
#include <cuda_runtime.h>
#include <cuda_bf16.h>
#include <cuda_fp16.h>
#include <math.h>
#include <stdint.h>

#define BB   32
#define CC   256
#define CQ   64
#define HW   4096
#define CHW  (CC*HW)
#define DD   (CQ*HW)

__device__ __half g_Qh[(size_t)BB*DD];
__device__ __half g_Kh[(size_t)BB*DD];
__device__ float g_energy[BB*BB];
__device__ float g_att[BB*BB];
__device__ uint4 g_y_bf[(size_t)BB*CHW/8];     // bf16 [i][c][p]
__device__ uint4 g_Wv_bf[CC*CC/8];             // bf16 [o][c]
__device__ uint16_t g_Wqk[2*128*256];          // bf16 [w][(Wh;Wl) 128 rows][c]

// ---------------------------------------------------------------------------
__device__ __forceinline__ void mma_bf16(
    float* c, const uint32_t* a, uint32_t b0, uint32_t b1)
{
    asm volatile(
        "mma.sync.aligned.m16n8k16.row.col.f32.bf16.bf16.f32 "
        "{%0,%1,%2,%3}, {%4,%5,%6,%7}, {%8,%9}, {%0,%1,%2,%3};"
        : "+f"(c[0]), "+f"(c[1]), "+f"(c[2]), "+f"(c[3])
        : "r"(a[0]), "r"(a[1]), "r"(a[2]), "r"(a[3]), "r"(b0), "r"(b1));
}
__device__ __forceinline__ void mma_f16(
    float* c, const uint32_t* a, uint32_t b0, uint32_t b1)
{
    asm volatile(
        "mma.sync.aligned.m16n8k16.row.col.f32.f16.f16.f32 "
        "{%0,%1,%2,%3}, {%4,%5,%6,%7}, {%8,%9}, {%0,%1,%2,%3};"
        : "+f"(c[0]), "+f"(c[1]), "+f"(c[2]), "+f"(c[3])
        : "r"(a[0]), "r"(a[1]), "r"(a[2]), "r"(a[3]), "r"(b0), "r"(b1));
}
__device__ __forceinline__ void ldsm_x4(
    uint32_t& r0, uint32_t& r1, uint32_t& r2, uint32_t& r3, uint32_t addr)
{
    asm volatile("ldmatrix.sync.aligned.m8n8.x4.shared.b16 {%0,%1,%2,%3}, [%4];"
        : "=r"(r0), "=r"(r1), "=r"(r2), "=r"(r3) : "r"(addr));
}
__device__ __forceinline__ void ldsm_x2(
    uint32_t& r0, uint32_t& r1, uint32_t addr)
{
    asm volatile("ldmatrix.sync.aligned.m8n8.x2.shared.b16 {%0,%1}, [%2];"
        : "=r"(r0), "=r"(r1) : "r"(addr));
}
__device__ __forceinline__ void ldsm_x4_t(
    uint32_t& r0, uint32_t& r1, uint32_t& r2, uint32_t& r3, uint32_t addr)
{
    asm volatile("ldmatrix.sync.aligned.m8n8.x4.trans.shared.b16 {%0,%1,%2,%3}, [%4];"
        : "=r"(r0), "=r"(r1), "=r"(r2), "=r"(r3) : "r"(addr));
}
__device__ __forceinline__ uint16_t bfb(__nv_bfloat16 h) {
    uint16_t u; memcpy(&u, &h, 2); return u;
}

// ---------------------------------------------------------------------------
// Prep (+ energy zeroing folded in)
__global__ __launch_bounds__(256) void k_prep(
    const float* __restrict__ Wq, const float* __restrict__ Wk,
    const float* __restrict__ Wv)
{
    if (blockIdx.x == 0) {
        #pragma unroll
        for (int r = 0; r < 4; r++) g_energy[r*256 + threadIdx.x] = 0.0f;
    }
    int t = blockIdx.x * 256 + threadIdx.x;
    int stride = gridDim.x * 256;
    for (int i = t; i < 2*CQ*CC; i += stride) {
        int w = i >> 14, rem = i & 16383;
        int o = rem >> 8, c = rem & 255;
        float f = (w ? Wk : Wq)[o*CC + c];
        __nv_bfloat16 h = __float2bfloat16(f);
        __nv_bfloat16 l = __float2bfloat16(f - __bfloat162float(h));
        g_Wqk[w*32768 + o*CC + c]      = bfb(h);
        g_Wqk[w*32768 + (o+64)*CC + c] = bfb(l);
    }
    __nv_bfloat16* wv = (__nv_bfloat16*)g_Wv_bf;
    for (int i = t; i < CC*CC; i += stride)
        wv[i] = __float2bfloat16(Wv[i]);
}

// ---------------------------------------------------------------------------
// Q/K projection, p-tile 128 + LDG register prefetch.
// D[128 Wrows][128 p] = [Wh;Wl] @ (xh then xl); out[o] = D[o]+D[o+64]+bias.
// 8 warps = 4(mg: Wrow group of 32) x 2(np: p group of 64).
__global__ __launch_bounds__(256) void k_proj_bf16(
    const float* __restrict__ x0, const float* __restrict__ x1,
    const float* __restrict__ bq, const float* __restrict__ bk)
{
    const int which = blockIdx.z;
    const int b  = blockIdx.y;
    const int p0 = blockIdx.x * 128;
    const float* __restrict__ x    = which ? x1 : x0;
    const float* __restrict__ bias = which ? bk : bq;
    __half* __restrict__ outp      = which ? g_Kh : g_Qh;

    const int t = threadIdx.x;
    const int lane = t & 31, warp = t >> 5;
    const int mg = warp >> 1, np = warp & 1;
    const int rsel = lane & 15, half = lane >> 4;
    const int gid = lane >> 2, tig = lane & 3;

    __shared__ __align__(16) char smraw[33792];
    uint16_t* ws = (uint16_t*)smraw;               // [128][40]  10240B
    uint16_t* xh = (uint16_t*)(smraw + 10240);     // [32][136]  8704B
    uint16_t* xl = (uint16_t*)(smraw + 18944);     // [32][136]  8704B
    float* stage = (float*)smraw;                  // [64][132]  33792B (reuse)
    const uint32_t ws_b = (uint32_t)__cvta_generic_to_shared(ws);
    const uint32_t xh_b = (uint32_t)__cvta_generic_to_shared(xh);
    const uint32_t xl_b = (uint32_t)__cvta_generic_to_shared(xl);

    float C[2][8][4];
    #pragma unroll
    for (int mf = 0; mf < 2; mf++)
        #pragma unroll
        for (int nf = 0; nf < 8; nf++)
            #pragma unroll
            for (int i = 0; i < 4; i++) C[mf][nf][i] = 0.0f;

    const uint16_t* wsrc = g_Wqk + which*32768;
    const float* xb = x + (size_t)b * CHW + p0;

    // prefetch registers
    uint4  wr[2];
    float4 xr[4];
    // thread's fixed fill coordinates
    const int w_row0 = t >> 2,  w_c8 = t & 3;            // +64 rows for wr[1]
    const int x_c[4]  = { t>>5, (256+t)>>5, (512+t)>>5, (768+t)>>5 };
    const int x_p4 = t & 31;

    // initial LDG (cc = 0)
    #pragma unroll
    for (int r = 0; r < 2; r++)
        wr[r] = *reinterpret_cast<const uint4*>(&wsrc[(w_row0 + r*64)*CC + w_c8*8]);
    #pragma unroll
    for (int r = 0; r < 4; r++)
        xr[r] = *reinterpret_cast<const float4*>(xb + (size_t)x_c[r] * HW + x_p4*4);

    for (int i = 0; i < 8; i++) {
        // convert current x regs to bf16 hi/lo pairs
        uint2 hp[4], lp[4];
        #pragma unroll
        for (int r = 0; r < 4; r++) {
            float4 v = xr[r];
            __nv_bfloat16 h0 = __float2bfloat16(v.x), h1 = __float2bfloat16(v.y);
            __nv_bfloat16 h2 = __float2bfloat16(v.z), h3 = __float2bfloat16(v.w);
            hp[r].x = (uint32_t)bfb(h0) | ((uint32_t)bfb(h1) << 16);
            hp[r].y = (uint32_t)bfb(h2) | ((uint32_t)bfb(h3) << 16);
            lp[r].x = (uint32_t)bfb(__float2bfloat16(v.x - __bfloat162float(h0)))
                    | ((uint32_t)bfb(__float2bfloat16(v.y - __bfloat162float(h1))) << 16);
            lp[r].y = (uint32_t)bfb(__float2bfloat16(v.z - __bfloat162float(h2)))
                    | ((uint32_t)bfb(__float2bfloat16(v.w - __bfloat162float(h3))) << 16);
        }
        __syncthreads();   // previous iteration's MMA done; buffers free
        #pragma unroll
        for (int r = 0; r < 2; r++)
            *reinterpret_cast<uint4*>(&ws[(w_row0 + r*64)*40 + w_c8*8]) = wr[r];
        #pragma unroll
        for (int r = 0; r < 4; r++) {
            *reinterpret_cast<uint2*>(&xh[x_c[r]*136 + x_p4*4]) = hp[r];
            *reinterpret_cast<uint2*>(&xl[x_c[r]*136 + x_p4*4]) = lp[r];
        }
        __syncthreads();   // buffers filled

        // prefetch next tile's globals (latency hides behind MMA below)
        if (i < 7) {
            const int cc = (i + 1) * 32;
            #pragma unroll
            for (int r = 0; r < 2; r++)
                wr[r] = *reinterpret_cast<const uint4*>(
                    &wsrc[(w_row0 + r*64)*CC + cc + w_c8*8]);
            #pragma unroll
            for (int r = 0; r < 4; r++)
                xr[r] = *reinterpret_cast<const float4*>(
                    xb + (size_t)(cc + x_c[r]) * HW + x_p4*4);
        }

        #pragma unroll
        for (int kk = 0; kk < 2; kk++) {
            uint32_t A[2][4];
            #pragma unroll
            for (int mf = 0; mf < 2; mf++) {
                uint32_t addr = ws_b +
                    (uint32_t)((mg*32 + mf*16 + rsel)*80 + kk*32 + half*16);
                ldsm_x4(A[mf][0], A[mf][1], A[mf][2], A[mf][3], addr);
            }
            uint32_t Bf[4][4];
            // hi pass
            #pragma unroll
            for (int n2 = 0; n2 < 4; n2++) {
                uint32_t addr = xh_b +
                    (uint32_t)((kk*16 + rsel)*272 + (np*64 + n2*16 + half*8)*2);
                ldsm_x4_t(Bf[n2][0], Bf[n2][1], Bf[n2][2], Bf[n2][3], addr);
            }
            #pragma unroll
            for (int mf = 0; mf < 2; mf++)
                #pragma unroll
                for (int nf = 0; nf < 8; nf++)
                    mma_bf16(C[mf][nf], A[mf],
                             Bf[nf>>1][(nf&1)*2], Bf[nf>>1][(nf&1)*2 + 1]);
            // lo pass
            #pragma unroll
            for (int n2 = 0; n2 < 4; n2++) {
                uint32_t addr = xl_b +
                    (uint32_t)((kk*16 + rsel)*272 + (np*64 + n2*16 + half*8)*2);
                ldsm_x4_t(Bf[n2][0], Bf[n2][1], Bf[n2][2], Bf[n2][3], addr);
            }
            #pragma unroll
            for (int mf = 0; mf < 2; mf++)
                #pragma unroll
                for (int nf = 0; nf < 8; nf++)
                    mma_bf16(C[mf][nf], A[mf],
                             Bf[nf>>1][(nf&1)*2], Bf[nf>>1][(nf&1)*2 + 1]);
        }
    }

    // Epilogue: combine hi (rows 0..63) + lo (rows 64..127) via smem RMW
    __syncthreads();
    if (mg < 2) {   // rows 0..63: store
        #pragma unroll
        for (int mf = 0; mf < 2; mf++)
            #pragma unroll
            for (int nf = 0; nf < 8; nf++) {
                int row = mg*32 + mf*16 + gid;
                int col = np*64 + nf*8 + tig*2;
                stage[row*132 + col]       = C[mf][nf][0];
                stage[row*132 + col + 1]   = C[mf][nf][1];
                stage[(row+8)*132 + col]   = C[mf][nf][2];
                stage[(row+8)*132 + col+1] = C[mf][nf][3];
            }
    }
    __syncthreads();
    if (mg >= 2) {  // rows 64..127: add (lo part for o = row-64)
        #pragma unroll
        for (int mf = 0; mf < 2; mf++)
            #pragma unroll
            for (int nf = 0; nf < 8; nf++) {
                int row = (mg-2)*32 + mf*16 + gid;
                int col = np*64 + nf*8 + tig*2;
                stage[row*132 + col]       += C[mf][nf][0];
                stage[row*132 + col + 1]   += C[mf][nf][1];
                stage[(row+8)*132 + col]   += C[mf][nf][2];
                stage[(row+8)*132 + col+1] += C[mf][nf][3];
            }
    }
    __syncthreads();
    #pragma unroll
    for (int r = 0; r < 16; r++) {
        int idx = r * 512 + t * 2;
        int o = idx >> 7, p = idx & 127;
        float bb = bias[o];
        __half2 v = __floats2half2_rn(stage[o*132 + p] + bb,
                                      stage[o*132 + p + 1] + bb);
        *reinterpret_cast<__half2*>(&outp[((size_t)b*CQ + o)*HW + p0 + p]) = v;
    }
}

// ---------------------------------------------------------------------------
// energy via fp16 mma (unchanged; measured 18us)
__global__ __launch_bounds__(256) void k_energy()
{
    __shared__ __align__(16) char smbuf[34816];
    uint16_t* Kt = (uint16_t*)smbuf;
    uint16_t* Qt = Kt + 32*264;
    float* red = (float*)smbuf;

    const int t = threadIdx.x;
    const int lane = t & 31, warp = t >> 5;
    const int gid = lane >> 2, tig = lane & 3;
    const int d0 = blockIdx.x * 2048;
    const uint32_t kt_b = (uint32_t)__cvta_generic_to_shared(Kt);
    const uint32_t qt_b = (uint32_t)__cvta_generic_to_shared(Qt);

    float C[2][4][4];
    #pragma unroll
    for (int mt = 0; mt < 2; mt++)
        #pragma unroll
        for (int nt = 0; nt < 4; nt++)
            #pragma unroll
            for (int i = 0; i < 4; i++) C[mt][nt][i] = 0.0f;

    for (int tile = 0; tile < 8; tile++) {
        const int dt = d0 + tile * 256;
        __syncthreads();
        #pragma unroll
        for (int r = 0; r < 4; r++) {
            int idx = r * 256 + t;
            int row = idx >> 5, c4 = idx & 31;
            *reinterpret_cast<uint4*>(&Kt[row*264 + c4*8]) =
                *reinterpret_cast<const uint4*>(&g_Kh[(size_t)row*DD + dt + c4*8]);
            *reinterpret_cast<uint4*>(&Qt[row*264 + c4*8]) =
                *reinterpret_cast<const uint4*>(&g_Qh[(size_t)row*DD + dt + c4*8]);
        }
        __syncthreads();
        #pragma unroll
        for (int ss = 0; ss < 2; ss++) {
            const int ds = (warp * 2 + ss) * 16;
            uint32_t A[2][4];
            #pragma unroll
            for (int mt = 0; mt < 2; mt++) {
                uint32_t addr = kt_b +
                    (uint32_t)(((mt*16 + (lane & 15))*264 + ds + (lane >> 4)*8) * 2);
                ldsm_x4(A[mt][0], A[mt][1], A[mt][2], A[mt][3], addr);
            }
            #pragma unroll
            for (int nt = 0; nt < 4; nt++) {
                uint32_t b0, b1;
                uint32_t addr = qt_b +
                    (uint32_t)(((nt*8 + (lane & 7))*264 + ds + ((lane >> 3) & 1)*8) * 2);
                ldsm_x2(b0, b1, addr);
                #pragma unroll
                for (int mt = 0; mt < 2; mt++)
                    mma_f16(C[mt][nt], A[mt], b0, b1);
            }
        }
    }
    __syncthreads();
    #pragma unroll
    for (int mt = 0; mt < 2; mt++)
        #pragma unroll
        for (int nt = 0; nt < 4; nt++) {
            int row = mt*16 + gid, col = nt*8 + tig*2;
            float* rw = red + warp*1024;
            rw[row*32 + col]       = C[mt][nt][0];
            rw[row*32 + col + 1]   = C[mt][nt][1];
            rw[(row+8)*32 + col]   = C[mt][nt][2];
            rw[(row+8)*32 + col+1] = C[mt][nt][3];
        }
    __syncthreads();
    #pragma unroll
    for (int r = 0; r < 4; r++) {
        int idx = r * 256 + t;
        float s = 0.f;
        #pragma unroll
        for (int w = 0; w < 8; w++) s += red[w*1024 + idx];
        atomicAdd(&g_energy[idx], s);
    }
}

// ---------------------------------------------------------------------------
__global__ void k_softmax(float* __restrict__ att_out)
{
    int i = threadIdx.x;
    if (i >= BB) return;
    float e[BB];
    float m = -INFINITY;
    #pragma unroll
    for (int j = 0; j < BB; j++) { e[j] = g_energy[i*BB + j]; m = fmaxf(m, e[j]); }
    float s = 0.f;
    #pragma unroll
    for (int j = 0; j < BB; j++) { e[j] = expf(e[j] - m); s += e[j]; }
    float inv = 1.0f / s;
    #pragma unroll
    for (int j = 0; j < BB; j++) {
        float a = e[j] * inv;
        g_att[i*BB + j] = a;
        if (att_out) att_out[i*BB + j] = a;
    }
}

// ---------------------------------------------------------------------------
__global__ __launch_bounds__(256) void k_mix(const float* __restrict__ x0)
{
    __shared__ float att_s[BB*BB];
    const int t = threadIdx.x;
    #pragma unroll
    for (int r = 0; r < 4; r++) att_s[r*256 + t] = g_att[r*256 + t];
    __syncthreads();

    const size_t cp = ((size_t)blockIdx.x * 256 + t) * 2;
    float2 acc[BB];
    #pragma unroll
    for (int i = 0; i < BB; i++) acc[i] = make_float2(0.f, 0.f);

    #pragma unroll
    for (int j = 0; j < BB; j++) {
        float2 v = *reinterpret_cast<const float2*>(&x0[(size_t)j * CHW + cp]);
        #pragma unroll
        for (int i = 0; i < BB; i++) {
            float a = att_s[i*BB + j];
            acc[i].x += a * v.x;
            acc[i].y += a * v.y;
        }
    }
    uint32_t* y2 = (uint32_t*)g_y_bf;
    const size_t base = (size_t)blockIdx.x * 256 + t;
    #pragma unroll
    for (int i = 0; i < BB; i++) {
        __nv_bfloat162 bv = __floats2bfloat162_rn(acc[i].x, acc[i].y);
        y2[(size_t)i * (CHW/2) + base] = *reinterpret_cast<uint32_t*>(&bv);
    }
}

// ---------------------------------------------------------------------------
// out = gamma*(Wv y + bv) + x1.  R11 EXACT (measured-best config).
__global__ __launch_bounds__(256) void k_out_bf16(
    const float* __restrict__ x1, const float* __restrict__ bv,
    const float* __restrict__ gamma, float* __restrict__ outp)
{
    const int b  = blockIdx.y;
    const int ot = blockIdx.z * 64;
    const int p0 = blockIdx.x * 128;
    const int t    = threadIdx.x;
    const int lane = t & 31, warp = t >> 5;
    const int wo = warp >> 2, wp = warp & 3;
    const int obase = wo * 32, pbw = wp * 32;
    const int gid = lane >> 2, tig = lane & 3;

    __shared__ __align__(16) uint16_t ws[64*40];
    __shared__ __align__(16) uint16_t ys[32*136];
    const uint32_t ws_b = (uint32_t)__cvta_generic_to_shared(ws);
    const uint32_t ys_b = (uint32_t)__cvta_generic_to_shared(ys);

    float C[2][4][4];
    #pragma unroll
    for (int mf = 0; mf < 2; mf++)
        #pragma unroll
        for (int nf = 0; nf < 4; nf++)
            #pragma unroll
            for (int i = 0; i < 4; i++) C[mf][nf][i] = 0.0f;

    const __nv_bfloat16* ybase = (const __nv_bfloat16*)g_y_bf + (size_t)b * CHW + p0;
    const __nv_bfloat16* wvb   = (const __nv_bfloat16*)g_Wv_bf;

    for (int cc = 0; cc < CC; cc += 32) {
        __syncthreads();
        {
            int row = t >> 2, ch = t & 3;
            *reinterpret_cast<uint4*>(&ws[row*40 + ch*8]) =
                *reinterpret_cast<const uint4*>(wvb + (size_t)(ot + row)*CC + cc + ch*8);
        }
        #pragma unroll
        for (int r = 0; r < 2; r++) {
            int idx = r * 256 + t;
            int row = idx >> 4, ch = idx & 15;
            *reinterpret_cast<uint4*>(&ys[row*136 + ch*8]) =
                *reinterpret_cast<const uint4*>(ybase + (size_t)(cc + row)*HW + ch*8);
        }
        __syncthreads();

        #pragma unroll
        for (int kk = 0; kk < 2; kk++) {
            const int rsel = lane & 15;
            const int half = lane >> 4;
            uint32_t A[2][4];
            #pragma unroll
            for (int mf = 0; mf < 2; mf++) {
                uint32_t addr = ws_b + (uint32_t)((obase + mf*16 + rsel)*80 + kk*32 + half*16);
                ldsm_x4(A[mf][0], A[mf][1], A[mf][2], A[mf][3], addr);
            }
            uint32_t Bf[2][4];
            #pragma unroll
            for (int n2 = 0; n2 < 2; n2++) {
                uint32_t addr = ys_b + (uint32_t)((kk*16 + rsel)*272 + (pbw + n2*16 + half*8)*2);
                ldsm_x4_t(Bf[n2][0], Bf[n2][1], Bf[n2][2], Bf[n2][3], addr);
            }
            #pragma unroll
            for (int mf = 0; mf < 2; mf++)
                #pragma unroll
                for (int nf = 0; nf < 4; nf++)
                    mma_bf16(C[mf][nf], A[mf],
                             Bf[nf>>1][(nf&1)*2], Bf[nf>>1][(nf&1)*2 + 1]);
        }
    }

    const float g = gamma[0];
    #pragma unroll
    for (int mf = 0; mf < 2; mf++) {
        const int o = ot + obase + mf*16 + gid;
        const float bv0 = bv[o], bv1 = bv[o + 8];
        #pragma unroll
        for (int nf = 0; nf < 4; nf++) {
            const int p = p0 + pbw + nf*8 + tig*2;
            size_t gi0 = ((size_t)b * CC + o) * HW + p;
            size_t gi1 = gi0 + (size_t)8 * HW;
            float2 xa = *reinterpret_cast<const float2*>(&x1[gi0]);
            float2 xc = *reinterpret_cast<const float2*>(&x1[gi1]);
            float2 r0, r1;
            r0.x = g * (C[mf][nf][0] + bv0) + xa.x;
            r0.y = g * (C[mf][nf][1] + bv0) + xa.y;
            r1.x = g * (C[mf][nf][2] + bv1) + xc.x;
            r1.y = g * (C[mf][nf][3] + bv1) + xc.y;
            *reinterpret_cast<float2*>(&outp[gi0]) = r0;
            *reinterpret_cast<float2*>(&outp[gi1]) = r1;
        }
    }
}

// ---------------------------------------------------------------------------
extern "C" void kernel_launch(void* const* d_in, const int* in_sizes, int n_in,
                              void* d_out, int out_size)
{
    const float* x0    = (const float*)d_in[0];
    const float* x1    = (const float*)d_in[1];
    const float* Wq    = (const float*)d_in[2];
    const float* bq    = (const float*)d_in[3];
    const float* Wk    = (const float*)d_in[4];
    const float* bk    = (const float*)d_in[5];
    const float* Wv    = (const float*)d_in[6];
    const float* bv    = (const float*)d_in[7];
    const float* gamma = (const float*)d_in[8];
    float* out = (float*)d_out;

    const long long out_elems = (long long)BB * CC * HW;
    float* att_out = ((long long)out_size >= out_elems + BB*BB)
                     ? out + out_elems : nullptr;

    k_prep<<<32, 256>>>(Wq, Wk, Wv);
    k_proj_bf16<<<dim3(HW/128, BB, 2), 256>>>(x0, x1, bq, bk);
    k_energy<<<DD/2048, 256>>>();
    k_softmax<<<1, 32>>>(att_out);
    k_mix<<<CHW/512, 256>>>(x0);
    k_out_bf16<<<dim3(HW/128, BB, CC/64), 256>>>(x1, bv, gamma, out);
}